// round 5
// baseline (speedup 1.0000x reference)
#include <cuda_runtime.h>
#include <math.h>

#define TT   1024
#define NA   512
#define MB   64
#define NM   32768                        // NA*MB floats per timestep slab
#define HM   16384                        // half-slab (one m-half) floats
#define HALF ((size_t)NM * TT)

typedef unsigned long long u64;

// ---------------- f32x2 packed helpers -------------------------------------------
__device__ __forceinline__ u64 splat2(float v) {
    u64 r; asm("mov.b64 %0, {%1, %1};" : "=l"(r) : "f"(v)); return r;
}
__device__ __forceinline__ void fma2(u64& d, u64 a, u64 b) {
    asm("fma.rn.f32x2 %0, %1, %2, %3;" : "=l"(d) : "l"(a), "l"(b), "l"(d));
}
__device__ __forceinline__ void unpack2(u64 v, float& lo, float& hi) {
    asm("mov.b64 {%0, %1}, %2;" : "=f"(lo), "=f"(hi) : "l"(v));
}

// ---------------- scratch (device globals; allocation forbidden) ------------------
__device__ float g_X2[(size_t)TT * NM];          // x transposed [t][n][m]; reused for Y
__device__ float g_P [(size_t)TT * NM];          // [t][a][m] = Wax@x + ba
__device__ float g_A [((size_t)TT + 1) * NM];    // [slot][mh][k][32]; slot0 = a0
__device__ int   g_done[2][TT + 1];              // per (m-half, step) counters

// ---------------- init: flags + seed a0 into slot 0 (half-split layout) -----------
__global__ void k_init(const float* __restrict__ a0) {
    int b = blockIdx.x;
    if (b == 128) {
        for (int i = threadIdx.x; i <= TT; i += blockDim.x) {
            g_done[0][i] = (i == 0) ? 64 : 0;
            g_done[1][i] = (i == 0) ? 64 : 0;
        }
    } else {
        int d  = b * 256 + threadIdx.x;          // dst index into slot 0
        int mh = d >> 14, k = (d >> 5) & 511, ml = d & 31;
        g_A[d] = a0[k * 64 + mh * 32 + ml];
    }
}

// ---------------- 32x32 tiled transpose -------------------------------------------
__device__ __forceinline__ void trans_body(const float* __restrict__ src,
                                           float* __restrict__ dst, int R, int C) {
    __shared__ float tile[32][33];
    int c0 = blockIdx.x * 32, r0 = blockIdx.y * 32;
    int tx = threadIdx.x, ty = threadIdx.y;
#pragma unroll
    for (int i = 0; i < 32; i += 8)
        tile[ty + i][tx] = src[(size_t)(r0 + ty + i) * C + (c0 + tx)];
    __syncthreads();
#pragma unroll
    for (int i = 0; i < 32; i += 8)
        dst[(size_t)(c0 + ty + i) * R + (r0 + tx)] = tile[tx][ty + i];
}
__global__ __launch_bounds__(256) void k_trans_x(const float* __restrict__ x) {
    trans_body(x, g_X2, NM, TT);          // [32768][1024] -> [1024][32768]
}
__global__ __launch_bounds__(256) void k_trans_y(float* __restrict__ out) {
    trans_body(g_X2, out, TT, NM);        // Y [1024][32768] -> [32768][1024]
}
// transpose for A: src cols are [mh][r][ml] permuted; remap dst column base
__global__ __launch_bounds__(256) void k_trans_a(float* __restrict__ out) {
    __shared__ float tile[32][33];
    int q   = blockIdx.x;                 // 32-col src block
    int r0  = blockIdx.y * 32;            // t block
    int mh  = q >> 9, r = q & 511;
    int c0  = q * 32;
    int cp0 = r * 64 + mh * 32;           // dst col base (contiguous over ml)
    const float* src = g_A + NM;          // slabs a_1..a_T
    int tx = threadIdx.x, ty = threadIdx.y;
#pragma unroll
    for (int i = 0; i < 32; i += 8)
        tile[ty + i][tx] = src[(size_t)(r0 + ty + i) * NM + c0 + tx];
    __syncthreads();
#pragma unroll
    for (int i = 0; i < 32; i += 8)
        out[(size_t)(cp0 + ty + i) * TT + r0 + tx] = tile[tx][ty + i];
}

// ---------------- batched GEMM with f32x2: C_t[128r x 64m] = W @ X_t (+bias) ------
// grid (4, 1024), 256 threads. Thread tile: 4 rows x 8 m (4 f32x2 pairs).
template <bool SOFTMAX, bool SPLITSRC>
__device__ __forceinline__ void gemm_body(const float* __restrict__ W,
                                          const float* __restrict__ bias,
                                          const float* __restrict__ Xbase,
                                          float* __restrict__ Ybase) {
    __shared__ float Ws[128][36];   // [row][k], padded: conflict-free stage, 16B STS
    __shared__ float Xs[32][64];    // [k][m]

    int t  = blockIdx.y;
    int rb = blockIdx.x;
    const float* Xsl = Xbase + (size_t)t * NM;
    float*       Y   = Ybase + (size_t)t * NM;
    int tid = threadIdx.x;
    int mq  = tid & 7;              // m0 = 8*mq
    int rq  = tid >> 3;             // r0 = 4*rq (32 groups)
    int r0  = rb * 128 + rq * 4;

    u64 acc[4][4];
#pragma unroll
    for (int i = 0; i < 4; i++)
#pragma unroll
        for (int j = 0; j < 4; j++) acc[i][j] = 0ull;

    for (int kt = 0; kt < 16; kt++) {
        __syncthreads();
        // stage W tile: 128 rows x 32 k = 1024 float4, 4/thread
#pragma unroll
        for (int p = 0; p < 4; p++) {
            int idx = tid + p * 256;
            int row = idx >> 3, k4 = idx & 7;
            *(float4*)&Ws[row][k4 * 4] =
                *(const float4*)&W[(size_t)(rb * 128 + row) * NA + kt * 32 + k4 * 4];
        }
        // stage X tile: 32 k x 64 m = 512 float4, 2/thread
#pragma unroll
        for (int p = 0; p < 2; p++) {
            int idx = tid + p * 256;
            int k = idx >> 4, m0 = (idx & 15) * 4;
            const float* src;
            if (SPLITSRC)
                src = Xsl + ((m0 >> 5) << 14) + (size_t)(kt * 32 + k) * 32 + (m0 & 31);
            else
                src = Xsl + (size_t)(kt * 32 + k) * MB + m0;
            *(float4*)&Xs[k][m0] = *(const float4*)src;
        }
        __syncthreads();
#pragma unroll 8
        for (int k = 0; k < 32; k++) {
            ulonglong2 xa = *(ulonglong2*)&Xs[k][mq * 8];
            ulonglong2 xb = *(ulonglong2*)&Xs[k][mq * 8 + 4];
#pragma unroll
            for (int i = 0; i < 4; i++) {
                u64 wp = splat2(Ws[rq * 4 + i][k]);
                fma2(acc[i][0], wp, xa.x);
                fma2(acc[i][1], wp, xa.y);
                fma2(acc[i][2], wp, xb.x);
                fma2(acc[i][3], wp, xb.y);
            }
        }
    }

#pragma unroll
    for (int i = 0; i < 4; i++) {
        float v[8];
        unpack2(acc[i][0], v[0], v[1]);
        unpack2(acc[i][1], v[2], v[3]);
        unpack2(acc[i][2], v[4], v[5]);
        unpack2(acc[i][3], v[6], v[7]);
        float b = bias[r0 + i];
#pragma unroll
        for (int j = 0; j < 8; j++) v[j] += b;

        if (SOFTMAX) {
            // softmax over batch axis m (64 values: 8 local x 8 lanes of mq)
            float mx = v[0];
#pragma unroll
            for (int j = 1; j < 8; j++) mx = fmaxf(mx, v[j]);
#pragma unroll
            for (int o = 1; o < 8; o <<= 1)
                mx = fmaxf(mx, __shfl_xor_sync(0xffffffffu, mx, o));
            float s = 0.f;
#pragma unroll
            for (int j = 0; j < 8; j++) { v[j] = __expf(v[j] - mx); s += v[j]; }
#pragma unroll
            for (int o = 1; o < 8; o <<= 1)
                s += __shfl_xor_sync(0xffffffffu, s, o);
            float inv = 1.0f / s;
#pragma unroll
            for (int j = 0; j < 8; j++) v[j] *= inv;
        }
        *(float4*)&Y[(size_t)(r0 + i) * MB + mq * 8]     = make_float4(v[0], v[1], v[2], v[3]);
        *(float4*)&Y[(size_t)(r0 + i) * MB + mq * 8 + 4] = make_float4(v[4], v[5], v[6], v[7]);
    }
}

__global__ __launch_bounds__(256) void k_gemmP(const float* __restrict__ Wax,
                                               const float* __restrict__ ba) {
    gemm_body<false, false>(Wax, ba, g_X2, g_P);
}
__global__ __launch_bounds__(256) void k_gemmY(const float* __restrict__ Wya,
                                               const float* __restrict__ by) {
    gemm_body<true, true>(Wya, by, g_A + NM, g_X2);
}

// ---------------- persistent recurrence: 128 CTAs x 128 thr, f32x2 row-pairs ------
// CTA = (8 rows) x (32 m-half). Waa pair-packed resident in SMEM; full a_prev
// half-slab staged once per step (dynamic smem 90,112 B; 1 CTA/SM, all resident).
#define RECUR_SMEM (16384 + 512 * 36 * 4)

__global__ __launch_bounds__(128) void k_recur(const float* __restrict__ Waa) {
    extern __shared__ char smraw[];
    float2* Wt2 = (float2*)smraw;              // [4 row-pairs][512 k]
    float*  As  = (float*)(smraw + 16384);     // [512 k][36] (padded)

    int bid = blockIdx.x;
    int rb  = bid >> 1;                        // 64 row blocks of 8
    int mh  = bid & 1;                         // m half
    int tid = threadIdx.x;
    int m   = tid & 31;
    int rp  = tid >> 5;                        // row-pair 0..3
    int r0  = rb * 8 + rp * 2;

    // stage Waa rows pair-packed: Wt2[rp][k] = {W[r0][k], W[r0+1][k]}
    {
        float* Wf = (float*)smraw;
#pragma unroll
        for (int p = 0; p < 8; p++) {
            int idx = tid + p * 128;
            int r = idx >> 7, k4 = idx & 127;
            float4 w = *(const float4*)&Waa[(size_t)(rb * 8 + r) * NA + k4 * 4];
            int base = (r >> 1) * 1024 + (r & 1);
            Wf[base + (k4 * 4 + 0) * 2] = w.x;
            Wf[base + (k4 * 4 + 1) * 2] = w.y;
            Wf[base + (k4 * 4 + 2) * 2] = w.z;
            Wf[base + (k4 * 4 + 3) * 2] = w.w;
        }
    }
    __syncthreads();

    const float2* wrow = Wt2 + rp * 512;

    for (int s = 0; s < TT; s++) {
        if (tid == 0)
            while (*(volatile int*)&g_done[mh][s] < 64) { }
        __syncthreads();
        __threadfence();

        // stage a_prev half-slab: contiguous 64KB, 32 float4/thread
        const float* Ap = g_A + (size_t)s * NM + (size_t)mh * HM;
#pragma unroll
        for (int i = 0; i < 32; i++) {
            int idx = tid + i * 128;           // 0..4095 float4
            int k = idx >> 3, c4 = idx & 7;
            *(float4*)&As[k * 36 + c4 * 4] = *(const float4*)&Ap[(size_t)idx * 4];
        }
        __syncthreads();

        u64 acc0 = 0ull, acc1 = 0ull;          // even-k / odd-k chains
#pragma unroll 8
        for (int kk = 0; kk < 512; kk += 4) {
            ulonglong2 wA = *(ulonglong2*)&wrow[kk];       // k, k+1 pairs
            ulonglong2 wB = *(ulonglong2*)&wrow[kk + 2];   // k+2, k+3 pairs
            u64 a0 = splat2(As[(kk + 0) * 36 + m]);
            u64 a1 = splat2(As[(kk + 1) * 36 + m]);
            u64 a2 = splat2(As[(kk + 2) * 36 + m]);
            u64 a3 = splat2(As[(kk + 3) * 36 + m]);
            fma2(acc0, wA.x, a0);
            fma2(acc1, wA.y, a1);
            fma2(acc0, wB.x, a2);
            fma2(acc1, wB.y, a3);
        }
        float e0, e1, o0, o1;
        unpack2(acc0, e0, e1);                 // lanes = rows (r0, r0+1)
        unpack2(acc1, o0, o1);
        float zr0 = e0 + o0, zr1 = e1 + o1;

        const float* Ps = g_P + (size_t)s * NM;
        float x0 = zr0 + Ps[(size_t)r0 * MB + mh * 32 + m];
        float x1 = zr1 + Ps[(size_t)(r0 + 1) * MB + mh * 32 + m];

        float* An = g_A + (size_t)(s + 1) * NM + (size_t)mh * HM;
        An[r0 * 32 + m]       = tanhf(x0);
        An[(r0 + 1) * 32 + m] = tanhf(x1);

        __threadfence();
        __syncthreads();
        if (tid == 0) atomicAdd(&g_done[mh][s + 1], 1);
    }
}

// ---------------- launch ----------------------------------------------------------
extern "C" void kernel_launch(void* const* d_in, const int* in_sizes, int n_in,
                              void* d_out, int out_size) {
    (void)in_sizes; (void)n_in; (void)out_size;
    const float* x   = (const float*)d_in[0];
    const float* a0  = (const float*)d_in[1];
    const float* Waa = (const float*)d_in[2];
    const float* Wax = (const float*)d_in[3];
    const float* Wya = (const float*)d_in[4];
    const float* ba  = (const float*)d_in[5];
    const float* by  = (const float*)d_in[6];
    float* out = (float*)d_out;

    cudaFuncSetAttribute(k_recur, cudaFuncAttributeMaxDynamicSharedMemorySize,
                         RECUR_SMEM);

    k_init<<<129, 256>>>(a0);
    k_trans_x<<<dim3(TT / 32, NM / 32), dim3(32, 8)>>>(x);     // x -> [t][n][m]
    k_gemmP<<<dim3(4, TT), 256>>>(Wax, ba);                    // P = Wax@X + ba
    k_recur<<<128, 128, RECUR_SMEM>>>(Waa);                    // a_t chain
    k_gemmY<<<dim3(4, TT), 256>>>(Wya, by);                    // Y = softmax(Wya@A+by)
    k_trans_a<<<dim3(NM / 32, TT / 32), dim3(32, 8)>>>(out);   // A -> [n][m][t]
    k_trans_y<<<dim3(NM / 32, TT / 32), dim3(32, 8)>>>(out + HALF);
}

// round 6
// speedup vs baseline: 1.6352x; 1.6352x over previous
#include <cuda_runtime.h>
#include <math.h>

#define TT   1024
#define NA   512
#define MB   64
#define NM   32768                       // NA*MB elements per timestep slab
#define HALF ((size_t)NM * TT)           // elements per output tensor

// ---------------- scratch (device globals; allocation is forbidden) -------------
__device__ float g_X2[(size_t)TT * NM];          // [t][n][m] transposed x; reused for Y
__device__ float g_P [(size_t)TT * NM];          // [t][a][m] = Wax@x + ba
__device__ float g_A [((size_t)TT + 1) * NM];    // slot 0 = a0; slot t+1 = a_{t+1}
__device__ int   g_done[TT + 1];                 // per-step completion counters

// ---------------- init: flags, seed a0 into slot 0 -------------------------------
__global__ void k_init(const float* __restrict__ a0) {
    if (blockIdx.x == 0) {
        for (int i = threadIdx.x; i <= TT; i += blockDim.x)
            g_done[i] = (i == 0) ? 128 : 0;
    } else {
        int idx = (blockIdx.x - 1) * 256 + threadIdx.x;
        g_A[idx] = a0[idx];
    }
}

// ---------------- 32x32 tiled transpose -------------------------------------------
__device__ __forceinline__ void trans_body(const float* __restrict__ src,
                                           float* __restrict__ dst, int R, int C) {
    __shared__ float tile[32][33];
    int c0 = blockIdx.x * 32, r0 = blockIdx.y * 32;
    int tx = threadIdx.x, ty = threadIdx.y;
#pragma unroll
    for (int i = 0; i < 32; i += 8)
        tile[ty + i][tx] = src[(size_t)(r0 + ty + i) * C + (c0 + tx)];
    __syncthreads();
#pragma unroll
    for (int i = 0; i < 32; i += 8)
        dst[(size_t)(c0 + ty + i) * R + (r0 + tx)] = tile[tx][ty + i];
}
__global__ __launch_bounds__(256) void k_trans_x(const float* __restrict__ x) {
    trans_body(x, g_X2, NM, TT);          // [32768][1024] -> [1024][32768]
}
__global__ __launch_bounds__(256) void k_trans_a(float* __restrict__ out) {
    trans_body(g_A + NM, out, TT, NM);    // [1024][32768] -> [32768][1024]
}
__global__ __launch_bounds__(256) void k_trans_y(float* __restrict__ out) {
    trans_body(g_X2, out, TT, NM);
}

// ---------------- batched GEMM: C_t[64 rows x 64 m] = W @ X_t (+bias) -------------
// grid = (8 row-blocks, 1024 t), 256 threads. Thread tile: 4 rows x 4 m.
template <bool SOFTMAX>
__device__ __forceinline__ void gemm_body(const float* __restrict__ W,
                                          const float* __restrict__ bias,
                                          const float* __restrict__ Xbase,
                                          float* __restrict__ Ybase) {
    __shared__ float Ws[64][32];   // [row][k]  8KB
    __shared__ float Xs[32][64];   // [k][m]    8KB

    int t   = blockIdx.y;
    int rb  = blockIdx.x;
    const float* X = Xbase + (size_t)t * NM;
    float*       Y = Ybase + (size_t)t * NM;
    int tid = threadIdx.x;
    int mq  = tid & 15;            // m0 = 4*mq
    int rq  = tid >> 4;            // r0 = 4*rq (16 groups)
    int r0  = rb * 64 + rq * 4;

    float acc[4][4];
#pragma unroll
    for (int i = 0; i < 4; i++)
#pragma unroll
        for (int j = 0; j < 4; j++) acc[i][j] = 0.f;

    for (int kt = 0; kt < 16; kt++) {
        __syncthreads();
        {
            int f4 = tid;
            int row = f4 >> 3, c4 = f4 & 7;
            *(float4*)&Ws[row][c4 * 4] =
                *(const float4*)&W[(size_t)(rb * 64 + row) * NA + kt * 32 + c4 * 4];
            f4 = tid + 256;
            row = f4 >> 3; c4 = f4 & 7;
            *(float4*)&Ws[row][c4 * 4] =
                *(const float4*)&W[(size_t)(rb * 64 + row) * NA + kt * 32 + c4 * 4];
        }
        {
            int f4 = tid;
            int k = f4 >> 4, m4 = f4 & 15;
            *(float4*)&Xs[k][m4 * 4] =
                *(const float4*)&X[(size_t)(kt * 32 + k) * MB + m4 * 4];
            f4 = tid + 256;
            k = f4 >> 4; m4 = f4 & 15;
            *(float4*)&Xs[k][m4 * 4] =
                *(const float4*)&X[(size_t)(kt * 32 + k) * MB + m4 * 4];
        }
        __syncthreads();
#pragma unroll 8
        for (int k = 0; k < 32; k++) {
            float4 xv = *(const float4*)&Xs[k][mq * 4];
#pragma unroll
            for (int i = 0; i < 4; i++) {
                float w = Ws[rq * 4 + i][k];
                acc[i][0] += w * xv.x;
                acc[i][1] += w * xv.y;
                acc[i][2] += w * xv.z;
                acc[i][3] += w * xv.w;
            }
        }
    }

    if (!SOFTMAX) {
#pragma unroll
        for (int i = 0; i < 4; i++) {
            float b = bias[r0 + i];
            float4 v = make_float4(acc[i][0] + b, acc[i][1] + b,
                                   acc[i][2] + b, acc[i][3] + b);
            *(float4*)&Y[(size_t)(r0 + i) * MB + mq * 4] = v;
        }
    } else {
#pragma unroll
        for (int i = 0; i < 4; i++) {
            float b  = bias[r0 + i];
            float v0 = acc[i][0] + b, v1 = acc[i][1] + b;
            float v2 = acc[i][2] + b, v3 = acc[i][3] + b;
            float mx = fmaxf(fmaxf(v0, v1), fmaxf(v2, v3));
#pragma unroll
            for (int o = 1; o < 16; o <<= 1)
                mx = fmaxf(mx, __shfl_xor_sync(0xffffffffu, mx, o));
            float e0 = __expf(v0 - mx), e1 = __expf(v1 - mx);
            float e2 = __expf(v2 - mx), e3 = __expf(v3 - mx);
            float s = e0 + e1 + e2 + e3;
#pragma unroll
            for (int o = 1; o < 16; o <<= 1)
                s += __shfl_xor_sync(0xffffffffu, s, o);
            float inv = 1.0f / s;
            *(float4*)&Y[(size_t)(r0 + i) * MB + mq * 4] =
                make_float4(e0 * inv, e1 * inv, e2 * inv, e3 * inv);
        }
    }
}

__global__ __launch_bounds__(256) void k_gemmP(const float* __restrict__ Wax,
                                               const float* __restrict__ ba) {
    gemm_body<false>(Wax, ba, g_X2, g_P);
}
__global__ __launch_bounds__(256) void k_gemmY(const float* __restrict__ Wya,
                                               const float* __restrict__ by) {
    gemm_body<true>(Wya, by, g_A + NM, g_X2);
}

// ---------------- persistent recurrence: 128 CTAs x 256 thr ----------------------
// CTA = 8 rows x 32 m-cols (one per thread). Waa rows resident in SMEM.
// Double-buffered a_prev k-tiles: stage kt+1 while computing kt (1 sync/ktile).
__global__ __launch_bounds__(256) void k_recur(const float* __restrict__ Waa) {
    __shared__ float Was[8][512];        // 16KB resident weights
    __shared__ float As[2][128][32];     // 2 x 16KB double-buffered a_prev tiles

    int bid = blockIdx.x;                // 0..127
    int rb  = bid >> 1;                  // 64 row blocks of 8
    int mh  = bid & 1;                   // m half
    int tid = threadIdx.x;
    int m   = tid & 31;                  // local m 0..31
    int r   = tid >> 5;                  // local row 0..7
    int r0  = rb * 8 + r;
    int mg  = mh * 32 + m;

    // load Waa rows once: 4096 floats = 1024 float4, 4 per thread
#pragma unroll
    for (int i = 0; i < 4; i++) {
        int f4  = tid + i * 256;
        int row = f4 >> 7;
        int c4  = f4 & 127;
        *(float4*)&Was[row][c4 * 4] =
            *(const float4*)&Waa[(size_t)(rb * 8 + row) * NA + c4 * 4];
    }
    __syncthreads();

    for (int s = 0; s < TT; s++) {
        if (tid == 0) {
            while (*(volatile int*)&g_done[s] < 128) { }
        }
        __syncthreads();

        const float* Ap = g_A + (size_t)s * NM;   // [k=512][m=64]

        // stage ktile 0 into buffer 0: 128 k x 32 m = 1024 float4, 4/thread
#pragma unroll
        for (int i = 0; i < 4; i++) {
            int idx = tid + i * 256;
            int k = idx >> 3, c4 = idx & 7;
            *(float4*)&As[0][k][c4 * 4] =
                *(const float4*)&Ap[(size_t)k * MB + mh * 32 + c4 * 4];
        }
        __syncthreads();

        float acc = 0.f;
        int buf = 0;
#pragma unroll
        for (int kt = 0; kt < 4; kt++) {
            // prefetch next ktile into the other buffer (overlaps compute)
            if (kt < 3) {
#pragma unroll
                for (int i = 0; i < 4; i++) {
                    int idx = tid + i * 256;
                    int k = idx >> 3, c4 = idx & 7;
                    *(float4*)&As[buf ^ 1][k][c4 * 4] =
                        *(const float4*)&Ap[(size_t)((kt + 1) * 128 + k) * MB +
                                            mh * 32 + c4 * 4];
                }
            }
            int koff = kt * 128;
#pragma unroll 8
            for (int k4 = 0; k4 < 32; k4++) {
                int kb = k4 * 4;
                float4 w = *(const float4*)&Was[r][koff + kb];   // warp-broadcast
                acc += w.x * As[buf][kb + 0][m];
                acc += w.y * As[buf][kb + 1][m];
                acc += w.z * As[buf][kb + 2][m];
                acc += w.w * As[buf][kb + 3][m];
            }
            __syncthreads();
            buf ^= 1;
        }

        size_t o = (size_t)r0 * MB + mg;
        g_A[(size_t)(s + 1) * NM + o] = tanhf(acc + g_P[(size_t)s * NM + o]);

        __threadfence();
        __syncthreads();
        if (tid == 0) atomicAdd(&g_done[s + 1], 1);
    }
}

// ---------------- launch ----------------------------------------------------------
extern "C" void kernel_launch(void* const* d_in, const int* in_sizes, int n_in,
                              void* d_out, int out_size) {
    (void)in_sizes; (void)n_in; (void)out_size;
    const float* x   = (const float*)d_in[0];
    const float* a0  = (const float*)d_in[1];
    const float* Waa = (const float*)d_in[2];
    const float* Wax = (const float*)d_in[3];
    const float* Wya = (const float*)d_in[4];
    const float* ba  = (const float*)d_in[5];
    const float* by  = (const float*)d_in[6];
    float* out = (float*)d_out;

    k_init<<<129, 256>>>(a0);
    k_trans_x<<<dim3(TT / 32, NM / 32), dim3(32, 8)>>>(x);     // x -> [t][n][m]
    k_gemmP<<<dim3(8, TT), 256>>>(Wax, ba);                    // P = Wax@X + ba
    k_recur<<<128, 256>>>(Waa);                                // a_t chain
    k_gemmY<<<dim3(8, TT), 256>>>(Wya, by);                    // Y = softmax(Wya@A+by)
    k_trans_a<<<dim3(NM / 32, TT / 32), dim3(32, 8)>>>(out);   // -> [n][m][t]
    k_trans_y<<<dim3(NM / 32, TT / 32), dim3(32, 8)>>>(out + HALF);
}

// round 7
// speedup vs baseline: 2.0690x; 1.2653x over previous
#include <cuda_runtime.h>
#include <math.h>

#define TT   1024
#define NA   512
#define MB   64
#define NM   32768                       // NA*MB elements per timestep slab
#define HALF ((size_t)NM * TT)           // elements per output tensor

// ---------------- scratch (device globals; allocation is forbidden) -------------
__device__ float g_X2[(size_t)TT * NM];          // [t][n][m] transposed x; reused for Y
__device__ float g_P [(size_t)TT * NM];          // [t][a][m] = Wax@x + ba
__device__ float g_A [((size_t)TT + 1) * NM];    // slot 0 = a0; slot t+1 = a_{t+1}
__device__ int   g_done[TT + 1];                 // per-step CTA-completion counters

// ---------------- init: flags, seed a0 into slot 0 -------------------------------
__global__ void k_init(const float* __restrict__ a0) {
    if (blockIdx.x == 0) {
        for (int i = threadIdx.x; i <= TT; i += blockDim.x)
            g_done[i] = (i == 0) ? 128 : 0;
    } else {
        int idx = (blockIdx.x - 1) * 256 + threadIdx.x;
        g_A[idx] = a0[idx];
    }
}

// ---------------- 32x32 tiled transpose -------------------------------------------
__device__ __forceinline__ void trans_body(const float* __restrict__ src,
                                           float* __restrict__ dst, int R, int C) {
    __shared__ float tile[32][33];
    int c0 = blockIdx.x * 32, r0 = blockIdx.y * 32;
    int tx = threadIdx.x, ty = threadIdx.y;
#pragma unroll
    for (int i = 0; i < 32; i += 8)
        tile[ty + i][tx] = src[(size_t)(r0 + ty + i) * C + (c0 + tx)];
    __syncthreads();
#pragma unroll
    for (int i = 0; i < 32; i += 8)
        dst[(size_t)(c0 + ty + i) * R + (r0 + tx)] = tile[tx][ty + i];
}
__global__ __launch_bounds__(256) void k_trans_x(const float* __restrict__ x) {
    trans_body(x, g_X2, NM, TT);          // [32768][1024] -> [1024][32768]
}
__global__ __launch_bounds__(256) void k_trans_a(float* __restrict__ out) {
    trans_body(g_A + NM, out, TT, NM);    // [1024][32768] -> [32768][1024]
}
__global__ __launch_bounds__(256) void k_trans_y(float* __restrict__ out) {
    trans_body(g_X2, out, TT, NM);
}

// ---------------- batched GEMM: C_t[64 rows x 64 m] = W @ X_t (+bias) -------------
template <bool SOFTMAX>
__device__ __forceinline__ void gemm_body(const float* __restrict__ W,
                                          const float* __restrict__ bias,
                                          const float* __restrict__ Xbase,
                                          float* __restrict__ Ybase) {
    __shared__ float Ws[64][32];
    __shared__ float Xs[32][64];

    int t   = blockIdx.y;
    int rb  = blockIdx.x;
    const float* X = Xbase + (size_t)t * NM;
    float*       Y = Ybase + (size_t)t * NM;
    int tid = threadIdx.x;
    int mq  = tid & 15;
    int rq  = tid >> 4;
    int r0  = rb * 64 + rq * 4;

    float acc[4][4];
#pragma unroll
    for (int i = 0; i < 4; i++)
#pragma unroll
        for (int j = 0; j < 4; j++) acc[i][j] = 0.f;

    for (int kt = 0; kt < 16; kt++) {
        __syncthreads();
        {
            int f4 = tid;
            int row = f4 >> 3, c4 = f4 & 7;
            *(float4*)&Ws[row][c4 * 4] =
                *(const float4*)&W[(size_t)(rb * 64 + row) * NA + kt * 32 + c4 * 4];
            f4 = tid + 256;
            row = f4 >> 3; c4 = f4 & 7;
            *(float4*)&Ws[row][c4 * 4] =
                *(const float4*)&W[(size_t)(rb * 64 + row) * NA + kt * 32 + c4 * 4];
        }
        {
            int f4 = tid;
            int k = f4 >> 4, m4 = f4 & 15;
            *(float4*)&Xs[k][m4 * 4] =
                *(const float4*)&X[(size_t)(kt * 32 + k) * MB + m4 * 4];
            f4 = tid + 256;
            k = f4 >> 4; m4 = f4 & 15;
            *(float4*)&Xs[k][m4 * 4] =
                *(const float4*)&X[(size_t)(kt * 32 + k) * MB + m4 * 4];
        }
        __syncthreads();
#pragma unroll 8
        for (int k = 0; k < 32; k++) {
            float4 xv = *(const float4*)&Xs[k][mq * 4];
#pragma unroll
            for (int i = 0; i < 4; i++) {
                float w = Ws[rq * 4 + i][k];
                acc[i][0] += w * xv.x;
                acc[i][1] += w * xv.y;
                acc[i][2] += w * xv.z;
                acc[i][3] += w * xv.w;
            }
        }
    }

    if (!SOFTMAX) {
#pragma unroll
        for (int i = 0; i < 4; i++) {
            float b = bias[r0 + i];
            float4 v = make_float4(acc[i][0] + b, acc[i][1] + b,
                                   acc[i][2] + b, acc[i][3] + b);
            *(float4*)&Y[(size_t)(r0 + i) * MB + mq * 4] = v;
        }
    } else {
#pragma unroll
        for (int i = 0; i < 4; i++) {
            float b  = bias[r0 + i];
            float v0 = acc[i][0] + b, v1 = acc[i][1] + b;
            float v2 = acc[i][2] + b, v3 = acc[i][3] + b;
            float mx = fmaxf(fmaxf(v0, v1), fmaxf(v2, v3));
#pragma unroll
            for (int o = 1; o < 16; o <<= 1)
                mx = fmaxf(mx, __shfl_xor_sync(0xffffffffu, mx, o));
            float e0 = __expf(v0 - mx), e1 = __expf(v1 - mx);
            float e2 = __expf(v2 - mx), e3 = __expf(v3 - mx);
            float s = e0 + e1 + e2 + e3;
#pragma unroll
            for (int o = 1; o < 16; o <<= 1)
                s += __shfl_xor_sync(0xffffffffu, s, o);
            float inv = 1.0f / s;
            *(float4*)&Y[(size_t)(r0 + i) * MB + mq * 4] =
                make_float4(e0 * inv, e1 * inv, e2 * inv, e3 * inv);
        }
    }
}

__global__ __launch_bounds__(256) void k_gemmP(const float* __restrict__ Wax,
                                               const float* __restrict__ ba) {
    gemm_body<false>(Wax, ba, g_X2, g_P);
}
__global__ __launch_bounds__(256) void k_gemmY(const float* __restrict__ Wya,
                                               const float* __restrict__ by) {
    gemm_body<true>(Wya, by, g_A + NM, g_X2);
}

// ---------------- persistent recurrence v3: 128 CTAs x 256 thr --------------------
// thread = (ks:4 k-split, r:8 rows, mq:8 m-quads). 4 acc chains per thread.
// Per-group staging + named bars; acquire-poll / release-red sync (no MEMBARs).
#define WPAD 516
#define SM_WAS (8 * WPAD)                 // 4128 floats
#define SM_AS  (512 * 32)                 // 16384 floats
#define SM_PART (3 * 64 * 4)              // 768 floats
#define RECUR_SMEM ((SM_WAS + SM_AS + SM_PART) * 4)

__global__ __launch_bounds__(256) void k_recur(const float* __restrict__ Waa) {
    extern __shared__ float sm[];
    float*  Was  = sm;                    // [8][WPAD]
    float*  As   = sm + SM_WAS;           // [512][32]
    float4* part = (float4*)(sm + SM_WAS + SM_AS);   // [3][64]

    int bid  = blockIdx.x;
    int rb   = bid >> 1;                  // 64 row blocks of 8
    int mh   = bid & 1;                   // m half
    int tid  = threadIdx.x;
    int ks   = tid >> 6;                  // k quarter 0..3
    int gtid = tid & 63;                  // = r*8 + mq
    int r    = gtid >> 3;
    int mq   = gtid & 7;
    int r0   = rb * 8 + r;

    // stage Waa rows once: 8 x 512 floats, padded stride WPAD
#pragma unroll
    for (int i = 0; i < 4; i++) {
        int f4  = tid + i * 256;          // 1024 float4
        int row = f4 >> 7, c4 = f4 & 127;
        float4 w = *(const float4*)&Waa[(size_t)(rb * 8 + row) * NA + c4 * 4];
        *(float4*)&Was[row * WPAD + c4 * 4] = w;
    }
    __syncthreads();

    const float* wrow = &Was[r * WPAD + ks * 128];
    float* dstbase = &As[ks * 128 * 32];

    for (int s = 0; s < TT; s++) {
        if (tid == 0) {
            int v;
            do {
                asm volatile("ld.acquire.gpu.global.u32 %0, [%1];"
                             : "=r"(v) : "l"(&g_done[s]));
            } while (v < 128);
        }
        __syncthreads();                  // transitive acquire for the CTA

        // each ks-group stages its own 128k x 32m region (16KB)
        const float* srcbase = g_A + (size_t)s * NM + mh * 32 + (size_t)ks * 128 * MB;
#pragma unroll
        for (int i = 0; i < 16; i++) {
            int idx = gtid + i * 64;      // 0..1023 float4
            int k = idx >> 3, c4 = idx & 7;
            *(float4*)&dstbase[k * 32 + c4 * 4] =
                *(const float4*)&srcbase[(size_t)k * MB + c4 * 4];
        }
        asm volatile("bar.sync %0, 64;" :: "r"(1 + ks) : "memory");

        // prefetch P (independent of the recurrence flag)
        size_t o = (size_t)r0 * MB + mh * 32 + mq * 4;
        float4 p4 = make_float4(0.f, 0.f, 0.f, 0.f);
        if (ks == 0) p4 = *(const float4*)&g_P[(size_t)s * NM + o];

        float ax = 0.f, ay = 0.f, az = 0.f, aw = 0.f;
        const float* asb = &As[ks * 128 * 32 + mq * 4];
#pragma unroll 8
        for (int k = 0; k < 128; k++) {
            float w  = wrow[k];
            float4 a = *(const float4*)&asb[k * 32];
            ax += w * a.x;  ay += w * a.y;
            az += w * a.z;  aw += w * a.w;
        }

        if (ks > 0) part[(ks - 1) * 64 + gtid] = make_float4(ax, ay, az, aw);
        __syncthreads();

        if (ks == 0) {
            float4 q0 = part[gtid], q1 = part[64 + gtid], q2 = part[128 + gtid];
            float4 outv;
            outv.x = tanhf(ax + q0.x + q1.x + q2.x + p4.x);
            outv.y = tanhf(ay + q0.y + q1.y + q2.y + p4.y);
            outv.z = tanhf(az + q0.z + q1.z + q2.z + p4.z);
            outv.w = tanhf(aw + q0.w + q1.w + q2.w + p4.w);
            *(float4*)&g_A[(size_t)(s + 1) * NM + o] = outv;
            asm volatile("bar.sync 5, 64;" ::: "memory");
            if (tid == 0)
                asm volatile("red.release.gpu.global.add.u32 [%0], %1;"
                             :: "l"(&g_done[s + 1]), "r"(1) : "memory");
        }
    }
}

// ---------------- launch ----------------------------------------------------------
extern "C" void kernel_launch(void* const* d_in, const int* in_sizes, int n_in,
                              void* d_out, int out_size) {
    (void)in_sizes; (void)n_in; (void)out_size;
    const float* x   = (const float*)d_in[0];
    const float* a0  = (const float*)d_in[1];
    const float* Waa = (const float*)d_in[2];
    const float* Wax = (const float*)d_in[3];
    const float* Wya = (const float*)d_in[4];
    const float* ba  = (const float*)d_in[5];
    const float* by  = (const float*)d_in[6];
    float* out = (float*)d_out;

    cudaFuncSetAttribute(k_recur, cudaFuncAttributeMaxDynamicSharedMemorySize,
                         RECUR_SMEM);

    k_init<<<129, 256>>>(a0);
    k_trans_x<<<dim3(TT / 32, NM / 32), dim3(32, 8)>>>(x);     // x -> [t][n][m]
    k_gemmP<<<dim3(8, TT), 256>>>(Wax, ba);                    // P = Wax@X + ba
    k_recur<<<128, 256, RECUR_SMEM>>>(Waa);                    // a_t chain
    k_gemmY<<<dim3(8, TT), 256>>>(Wya, by);                    // Y = softmax(Wya@A+by)
    k_trans_a<<<dim3(NM / 32, TT / 32), dim3(32, 8)>>>(out);   // -> [n][m][t]
    k_trans_y<<<dim3(NM / 32, TT / 32), dim3(32, 8)>>>(out + HALF);
}

// round 8
// speedup vs baseline: 2.3975x; 1.1588x over previous
#include <cuda_runtime.h>
#include <math.h>

#define TT   1024
#define NA   512
#define MB   64
#define NM   32768                       // NA*MB elements per timestep slab
#define HALF ((size_t)NM * TT)           // elements per output tensor

// ---------------- scratch (device globals; allocation is forbidden) -------------
__device__ float g_X2[(size_t)TT * NM];          // [t][n][m] transposed x; reused for Y
__device__ float g_P [(size_t)TT * NM];          // [t][a][m] = Wax@x + ba
__device__ float g_A [((size_t)TT + 1) * NM];    // slot 0 = a0; slot t+1 = a_{t+1}
__device__ int   g_doneq[2][TT + 1][8];          // [mh][slot][octant] counters (8 = done)

// ---------------- init: flags, seed a0 into slot 0 -------------------------------
__global__ void k_init(const float* __restrict__ a0) {
    if (blockIdx.x == 0) {
        int total = 2 * (TT + 1) * 8;
        int* f = &g_doneq[0][0][0];
        for (int i = threadIdx.x; i < total; i += blockDim.x) {
            int s = (i >> 3) % (TT + 1);
            f[i] = (s == 0) ? 8 : 0;
        }
    } else {
        int idx = (blockIdx.x - 1) * 256 + threadIdx.x;
        g_A[idx] = a0[idx];
    }
}

// ---------------- 32x32 tiled transpose -------------------------------------------
__device__ __forceinline__ void trans_body(const float* __restrict__ src,
                                           float* __restrict__ dst, int R, int C) {
    __shared__ float tile[32][33];
    int c0 = blockIdx.x * 32, r0 = blockIdx.y * 32;
    int tx = threadIdx.x, ty = threadIdx.y;
#pragma unroll
    for (int i = 0; i < 32; i += 8)
        tile[ty + i][tx] = src[(size_t)(r0 + ty + i) * C + (c0 + tx)];
    __syncthreads();
#pragma unroll
    for (int i = 0; i < 32; i += 8)
        dst[(size_t)(c0 + ty + i) * R + (r0 + tx)] = tile[tx][ty + i];
}
__global__ __launch_bounds__(256) void k_trans_x(const float* __restrict__ x) {
    trans_body(x, g_X2, NM, TT);          // [32768][1024] -> [1024][32768]
}
__global__ __launch_bounds__(256) void k_trans_a(float* __restrict__ out) {
    trans_body(g_A + NM, out, TT, NM);    // [1024][32768] -> [32768][1024]
}
__global__ __launch_bounds__(256) void k_trans_y(float* __restrict__ out) {
    trans_body(g_X2, out, TT, NM);
}

// ---------------- batched GEMM: C_t[64 rows x 64 m] = W @ X_t (+bias) -------------
template <bool SOFTMAX>
__device__ __forceinline__ void gemm_body(const float* __restrict__ W,
                                          const float* __restrict__ bias,
                                          const float* __restrict__ Xbase,
                                          float* __restrict__ Ybase) {
    __shared__ float Ws[64][32];
    __shared__ float Xs[32][64];

    int t   = blockIdx.y;
    int rb  = blockIdx.x;
    const float* X = Xbase + (size_t)t * NM;
    float*       Y = Ybase + (size_t)t * NM;
    int tid = threadIdx.x;
    int mq  = tid & 15;
    int rq  = tid >> 4;
    int r0  = rb * 64 + rq * 4;

    float acc[4][4];
#pragma unroll
    for (int i = 0; i < 4; i++)
#pragma unroll
        for (int j = 0; j < 4; j++) acc[i][j] = 0.f;

    for (int kt = 0; kt < 16; kt++) {
        __syncthreads();
        {
            int f4 = tid;
            int row = f4 >> 3, c4 = f4 & 7;
            *(float4*)&Ws[row][c4 * 4] =
                *(const float4*)&W[(size_t)(rb * 64 + row) * NA + kt * 32 + c4 * 4];
            f4 = tid + 256;
            row = f4 >> 3; c4 = f4 & 7;
            *(float4*)&Ws[row][c4 * 4] =
                *(const float4*)&W[(size_t)(rb * 64 + row) * NA + kt * 32 + c4 * 4];
        }
        {
            int f4 = tid;
            int k = f4 >> 4, m4 = f4 & 15;
            *(float4*)&Xs[k][m4 * 4] =
                *(const float4*)&X[(size_t)(kt * 32 + k) * MB + m4 * 4];
            f4 = tid + 256;
            k = f4 >> 4; m4 = f4 & 15;
            *(float4*)&Xs[k][m4 * 4] =
                *(const float4*)&X[(size_t)(kt * 32 + k) * MB + m4 * 4];
        }
        __syncthreads();
#pragma unroll 8
        for (int k = 0; k < 32; k++) {
            float4 xv = *(const float4*)&Xs[k][mq * 4];
#pragma unroll
            for (int i = 0; i < 4; i++) {
                float w = Ws[rq * 4 + i][k];
                acc[i][0] += w * xv.x;
                acc[i][1] += w * xv.y;
                acc[i][2] += w * xv.z;
                acc[i][3] += w * xv.w;
            }
        }
    }

    if (!SOFTMAX) {
#pragma unroll
        for (int i = 0; i < 4; i++) {
            float b = bias[r0 + i];
            float4 v = make_float4(acc[i][0] + b, acc[i][1] + b,
                                   acc[i][2] + b, acc[i][3] + b);
            *(float4*)&Y[(size_t)(r0 + i) * MB + mq * 4] = v;
        }
    } else {
#pragma unroll
        for (int i = 0; i < 4; i++) {
            float b  = bias[r0 + i];
            float v0 = acc[i][0] + b, v1 = acc[i][1] + b;
            float v2 = acc[i][2] + b, v3 = acc[i][3] + b;
            float mx = fmaxf(fmaxf(v0, v1), fmaxf(v2, v3));
#pragma unroll
            for (int o = 1; o < 16; o <<= 1)
                mx = fmaxf(mx, __shfl_xor_sync(0xffffffffu, mx, o));
            float e0 = __expf(v0 - mx), e1 = __expf(v1 - mx);
            float e2 = __expf(v2 - mx), e3 = __expf(v3 - mx);
            float s = e0 + e1 + e2 + e3;
#pragma unroll
            for (int o = 1; o < 16; o <<= 1)
                s += __shfl_xor_sync(0xffffffffu, s, o);
            float inv = 1.0f / s;
            *(float4*)&Y[(size_t)(r0 + i) * MB + mq * 4] =
                make_float4(e0 * inv, e1 * inv, e2 * inv, e3 * inv);
        }
    }
}

__global__ __launch_bounds__(256) void k_gemmP(const float* __restrict__ Wax,
                                               const float* __restrict__ ba) {
    gemm_body<false>(Wax, ba, g_X2, g_P);
}
__global__ __launch_bounds__(256) void k_gemmY(const float* __restrict__ Wya,
                                               const float* __restrict__ by) {
    gemm_body<true>(Wya, by, g_A + NM, g_X2);
}

// ---------------- persistent recurrence v4: 128 CTAs x 256 thr --------------------
// warp w = k-octant [64k]; lane = m. Thread: 8 rows x 1 m x 64 k, 8 acc chains.
// Warps proceed independently (per-octant flags) -> L2 stream overlaps compute.
#define AST 33
#define SM_WAS (8 * 512)                  // 16 KB
#define SM_AS  (512 * AST)                // 67584 B
#define SM_PART (8 * 8 * 32)              // 8 KB
#define RECUR_SMEM ((SM_WAS + SM_AS + SM_PART) * 4)

__global__ __launch_bounds__(256) void k_recur(const float* __restrict__ Waa) {
    extern __shared__ float sm[];
    float* Was  = sm;                     // [8 rows][512 k]
    float* As   = sm + SM_WAS;            // [512 k][33]
    float* part = sm + SM_WAS + SM_AS;    // [8 ks][8 r][32 m]

    int bid = blockIdx.x;
    int rb  = bid >> 1;                   // 64 row blocks of 8
    int mh  = bid & 1;                    // m half
    int tid = threadIdx.x;
    int w   = tid >> 5;                   // warp = octant 0..7
    int l   = tid & 31;                   // lane = m

    // stage Waa rows once: 8 x 512 = 1024 float4, 4/thread
#pragma unroll
    for (int i = 0; i < 4; i++) {
        int f4  = tid + i * 256;
        int row = f4 >> 7, c4 = f4 & 127;
        float4 v = *(const float4*)&Waa[(size_t)(rb * 8 + row) * NA + c4 * 4];
        *(float4*)&Was[row * 512 + c4 * 4] = v;
    }
    __syncthreads();

    const size_t o  = (size_t)(rb * 8 + w) * MB + mh * 32 + l;   // my output elem
    const int*   fl = &g_doneq[mh][0][w];
    float* dst = As + w * 64 * AST;
    const float* ab = As + w * 64 * AST + l;
    const float* wb = Was + w * 64;

    for (int s = 0; s < TT; s++) {
        // prefetch P (independent of flags; hides L2 latency)
        float pv = g_P[(size_t)s * NM + o];

        // wait for octant w of slot s (all lanes poll; coalesced acquire)
        {
            int v;
            do {
                asm volatile("ld.acquire.gpu.global.u32 %0, [%1];"
                             : "=r"(v) : "l"(fl + (size_t)s * 8));
            } while (v < 8);
        }
        __syncwarp();

        // stage my octant: 64 k x 32 m = 512 float4, 16 per lane
        const float* src = g_A + (size_t)s * NM + (size_t)w * 64 * MB + mh * 32;
#pragma unroll
        for (int i = 0; i < 16; i++) {
            int idx = l + i * 32;
            int kq = idx >> 3, c4 = idx & 7;
            float4 a4 = *(const float4*)&src[(size_t)kq * MB + c4 * 4];
            float* d = &dst[kq * AST + c4 * 4];
            d[0] = a4.x; d[1] = a4.y; d[2] = a4.z; d[3] = a4.w;
        }
        __syncwarp();

        // compute: 8 rows x 64 k, m = lane
        float acc[8];
#pragma unroll
        for (int r = 0; r < 8; r++) acc[r] = 0.f;
#pragma unroll
        for (int u = 0; u < 64; u += 4) {
            float a0 = ab[(u + 0) * AST];
            float a1 = ab[(u + 1) * AST];
            float a2 = ab[(u + 2) * AST];
            float a3 = ab[(u + 3) * AST];
#pragma unroll
            for (int r = 0; r < 8; r++) {
                float4 wv = *(const float4*)&wb[r * 512 + u];   // warp-uniform
                acc[r] += wv.x * a0;
                acc[r] += wv.y * a1;
                acc[r] += wv.z * a2;
                acc[r] += wv.w * a3;
            }
        }
#pragma unroll
        for (int r = 0; r < 8; r++)
            part[(w * 8 + r) * 32 + l] = acc[r];
        __syncthreads();

        // reduce over 8 octants: thread (w,l) owns output (row w, m l)
        float z = pv;
#pragma unroll
        for (int ks = 0; ks < 8; ks++)
            z += part[(ks * 8 + w) * 32 + l];
        g_A[(size_t)(s + 1) * NM + o] = tanhf(z);

        __syncthreads();
        if (tid == 0)
            asm volatile("red.release.gpu.global.add.u32 [%0], %1;"
                         :: "l"(&g_doneq[mh][s + 1][rb >> 3]), "r"(1) : "memory");
    }
}

// ---------------- launch ----------------------------------------------------------
extern "C" void kernel_launch(void* const* d_in, const int* in_sizes, int n_in,
                              void* d_out, int out_size) {
    (void)in_sizes; (void)n_in; (void)out_size;
    const float* x   = (const float*)d_in[0];
    const float* a0  = (const float*)d_in[1];
    const float* Waa = (const float*)d_in[2];
    const float* Wax = (const float*)d_in[3];
    const float* Wya = (const float*)d_in[4];
    const float* ba  = (const float*)d_in[5];
    const float* by  = (const float*)d_in[6];
    float* out = (float*)d_out;

    cudaFuncSetAttribute(k_recur, cudaFuncAttributeMaxDynamicSharedMemorySize,
                         RECUR_SMEM);

    k_init<<<129, 256>>>(a0);
    k_trans_x<<<dim3(TT / 32, NM / 32), dim3(32, 8)>>>(x);     // x -> [t][n][m]
    k_gemmP<<<dim3(8, TT), 256>>>(Wax, ba);                    // P = Wax@X + ba
    k_recur<<<128, 256, RECUR_SMEM>>>(Waa);                    // a_t chain
    k_gemmY<<<dim3(8, TT), 256>>>(Wya, by);                    // Y = softmax(Wya@A+by)
    k_trans_a<<<dim3(NM / 32, TT / 32), dim3(32, 8)>>>(out);   // -> [n][m][t]
    k_trans_y<<<dim3(NM / 32, TT / 32), dim3(32, 8)>>>(out + HALF);
}